// round 11
// baseline (speedup 1.0000x reference)
#include <cuda_runtime.h>
#include <cuda_fp16.h>

// 3D LUT trilinear interpolation — round 8.
// R7 evidence: L1tex 79%, issue 62.9%. LDS crossbar (16 random LDS.32/iter,
// conflict ~3.4) is ~77% of the L1tex pipe; structural byte reductions are
// blocked by the 227KB smem cap (quad table needs 264KB). This round:
//   (a) batched gather: compute 4 bases, then issue all 16 LDS back-to-back
//   (b) magic-number floor: removes 24 F2I/I2F (20-cyc class) per iter from
//       the LDS address critical path
// Keep: half2 b-pair table (4 taps/px-ch), channel-sibling L2 sharing of x,
// next-iteration prefetch.

#define LUT_D  33
#define LUT_D2 (33 * 33)
#define LUT_D3 (33 * 33 * 33)      // 35937
#define HW     (1024 * 1024)
#define NBATCH 8
#define NPIX   (NBATCH * HW)       // 8388608
#define NGROUPS (NPIX / 4)         // 2097152 float4 groups
#define NREGION 148
#define SMEM_BYTES (LUT_D3 * 4)    // 143748 B of half2 b-pairs

#define MAGIC 12582912.0f          // 2^23 + 2^22

// Compute LDS base index + fractional weights for one pixel, all fixed-lat ALU.
__device__ __forceinline__ void lut_setup(float r, float g, float b,
                                          int& base, float& fr, float& fg, float& fb)
{
    float vr = __saturatef(r) * 32.0f;
    float vg = __saturatef(g) * 32.0f;
    float vb = __saturatef(b) * 32.0f;

    // floor via round(v - 0.5): halfway cases round to even, which yields
    // frac==1.0 on the lower base — mathematically identical lerp result.
    float tr = (vr - 0.5f) + MAGIC;
    float tg = (vg - 0.5f) + MAGIC;
    float tb = (vb - 0.5f) + MAGIC;

    int ir = min(__float_as_int(tr) - 0x4B400000, LUT_D - 2);
    int ig = min(__float_as_int(tg) - 0x4B400000, LUT_D - 2);
    int ib = min(__float_as_int(tb) - 0x4B400000, LUT_D - 2);

    fr = vr - fminf(tr - MAGIC, 32.0f - 1.0f);
    fg = vg - fminf(tg - MAGIC, 32.0f - 1.0f);
    fb = vb - fminf(tb - MAGIC, 32.0f - 1.0f);

    base = ir * LUT_D2 + ig * LUT_D + ib;
}

__global__ __launch_bounds__(1024, 1)
void TrilinearInterpolation_82171314307385_kernel(const float* __restrict__ lut,
                                                  const float* __restrict__ x,
                                                  float* __restrict__ out)
{
    extern __shared__ half2 slut[];

    const int c      = blockIdx.x % 3;
    const int region = blockIdx.x / 3;

    const float* lutc = lut + c * LUT_D3;
    for (int i = threadIdx.x; i < LUT_D3; i += blockDim.x) {
        float a0 = lutc[i];
        float a1 = lutc[min(i + 1, LUT_D3 - 1)];
        slut[i] = __floats2half2_rn(a0, a1);
    }
    __syncthreads();

    const int start = (int)(((long long)region * NGROUPS) / NREGION);
    const int end   = (int)(((long long)(region + 1) * NGROUPS) / NREGION);

    int idx = start + (int)threadIdx.x;
    if (idx >= end) return;

    // prologue: load first group
    int p  = idx << 2;
    int bi = p >> 20;
    int hw = p & (HW - 1);
    const float* xb0 = x + (size_t)(bi * 3) * HW + hw;
    float4 xr = *(const float4*)(xb0);
    float4 xg = *(const float4*)(xb0 + HW);
    float4 xb = *(const float4*)(xb0 + 2 * HW);

    while (true) {
        int nidx = idx + 1024;
        float4 nr, ng, nb;
        bool have_next = (nidx < end);
        if (have_next) {
            int np  = nidx << 2;
            int nbi = np >> 20;
            int nhw = np & (HW - 1);
            const float* nxb0 = x + (size_t)(nbi * 3) * HW + nhw;
            nr = *(const float4*)(nxb0);
            ng = *(const float4*)(nxb0 + HW);
            nb = *(const float4*)(nxb0 + 2 * HW);
        }

        // ---- phase 1: all address math (fixed-lat ALU only) ----
        int   base[4];
        float fr[4], fg[4], fb[4];
        lut_setup(xr.x, xg.x, xb.x, base[0], fr[0], fg[0], fb[0]);
        lut_setup(xr.y, xg.y, xb.y, base[1], fr[1], fg[1], fb[1]);
        lut_setup(xr.z, xg.z, xb.z, base[2], fr[2], fg[2], fb[2]);
        lut_setup(xr.w, xg.w, xb.w, base[3], fr[3], fg[3], fb[3]);

        // ---- phase 2: all 16 LDS issued back-to-back ----
        half2 q00[4], q01[4], q10[4], q11[4];
        #pragma unroll
        for (int k = 0; k < 4; k++) {
            q00[k] = slut[base[k]];
            q01[k] = slut[base[k] + LUT_D];
            q10[k] = slut[base[k] + LUT_D2];
            q11[k] = slut[base[k] + LUT_D2 + LUT_D];
        }

        // ---- phase 3: lerp trees ----
        float o[4];
        #pragma unroll
        for (int k = 0; k < 4; k++) {
            float2 a00 = __half22float2(q00[k]);
            float2 a01 = __half22float2(q01[k]);
            float2 a10 = __half22float2(q10[k]);
            float2 a11 = __half22float2(q11[k]);

            float c00 = fmaf(fb[k], a00.y - a00.x, a00.x);
            float c01 = fmaf(fb[k], a01.y - a01.x, a01.x);
            float c10 = fmaf(fb[k], a10.y - a10.x, a10.x);
            float c11 = fmaf(fb[k], a11.y - a11.x, a11.x);

            float c0 = fmaf(fg[k], c01 - c00, c00);
            float c1 = fmaf(fg[k], c11 - c10, c10);
            o[k] = fmaf(fr[k], c1 - c0, c0);
        }

        *(float4*)(out + (size_t)(bi * 3 + c) * HW + hw) =
            make_float4(o[0], o[1], o[2], o[3]);

        if (!have_next) break;
        idx = nidx;
        p  = idx << 2;
        bi = p >> 20;
        hw = p & (HW - 1);
        xr = nr; xg = ng; xb = nb;
    }
}

extern "C" void kernel_launch(void* const* d_in, const int* in_sizes, int n_in,
                              void* d_out, int out_size)
{
    const float* lut = (const float*)d_in[0];
    const float* x   = (const float*)d_in[1];
    float* out       = (float*)d_out;
    (void)in_sizes; (void)n_in; (void)out_size;

    cudaFuncSetAttribute(TrilinearInterpolation_82171314307385_kernel,
                         cudaFuncAttributeMaxDynamicSharedMemorySize, SMEM_BYTES);

    TrilinearInterpolation_82171314307385_kernel<<<3 * NREGION, 1024, SMEM_BYTES>>>(lut, x, out);
}